// round 15
// baseline (speedup 1.0000x reference)
#include <cuda_runtime.h>
#include <cuda_bf16.h>
#include <cstdint>

typedef unsigned int uint;

// ---------------------------------------------------------------------------
// B=64, Cin=64, T=300, V=25, K=3, Cout=64
//   x: [64][64][300][25]; W: [192][64] (o=k*64+c); A: [3][25][25]
//   out: [64][64][300][25]
// xc scratch: tf32 bits in GRAPH OPERAND LAYOUT [r][88]:
//   r = (b*64+c)*300 + t ; column = cperm(k*26+v); pads zero (static init,
//   never written). Graph loader = pure uint4 copy (no div/cvt/perm).
// Both GEMMs: mma.sync m16n8k8 TF32 (cvt.rna), pair-permuted LDS.64 operands.
// ---------------------------------------------------------------------------

__device__ uint  g_xc[108134400];         // 1228800 * 88 (432 MB)
__device__ float g_bsum[16384];           // [instance(b*64+c)][slot 0..3]
__device__ float g_bsq [16384];
__device__ float g_scale[64];
__device__ float g_shift[64];
__device__ uint  g_Wt[12288];             // W as tf32 bits, [o][ci]
__device__ uint  g_At[2816];              // A' tf32, [w 32][88] permuted, pads 0

__device__ __forceinline__ uint f2tf(float f) {
    uint u; asm("cvt.rna.tf32.f32 %0, %1;" : "=r"(u) : "f"(f)); return u;
}
__device__ __forceinline__ void mma_tf32(float* c, const uint* a, const uint* b) {
    asm volatile(
        "mma.sync.aligned.m16n8k8.row.col.f32.tf32.tf32.f32 "
        "{%0,%1,%2,%3}, {%4,%5,%6,%7}, {%8,%9}, {%0,%1,%2,%3};"
        : "+f"(c[0]), "+f"(c[1]), "+f"(c[2]), "+f"(c[3])
        : "r"(a[0]), "r"(a[1]), "r"(a[2]), "r"(a[3]), "r"(b[0]), "r"(b[1]));
}
// column permutation within each 8-group: [0,4,1,5,2,6,3,7]
__device__ __forceinline__ int cperm(int c) {
    return (c & ~7) | (((c & 3) << 1) | ((c & 4) >> 2));
}

// ---------------------------------------------------------------------------
// k_prep: W -> tf32; A -> permuted tf32 operand [32][88]; zero BN slots.
// Idempotent; launched 2x so ncu capture slot (launch index 3) = k_graph.
// ---------------------------------------------------------------------------
__global__ void k_prep(const float* __restrict__ W, const float* __restrict__ A) {
    const int i = blockIdx.x * 256 + threadIdx.x;
    if (i < 16384) { g_bsum[i] = 0.f; g_bsq[i] = 0.f; }
    if (i < 12288) g_Wt[i] = f2tf(W[i]);
    if (i < 2816) {
        const int w = i / 88, pc = i - w * 88;
        const int u = pc & 7;                        // inverse of cperm
        const int col = (pc & ~7) | ((u & 1) ? ((u >> 1) + 4) : (u >> 1));
        float val = 0.f;
        if (col < 80) {
            const int k = col / 26, v = col - 26 * k;
            if (w < 25 && k < 3 && v < 25) val = A[(k * 25 + v) * 25 + w];
        }
        g_At[i] = f2tf(val);
    }
}

// ---------------------------------------------------------------------------
// k_conv: 64 p x 192 o per CTA, K=64 tf32. 256 thr = 2 M-warps x 4 N-warps
// (warp tile 32x48). grid 7500, 2 CTAs/SM.
// smem: bias 768 | sX [64][72] tf32 | sW [192][72] tf32
// Epilogue: f2tf + scatter into graph layout [r][88].
// ---------------------------------------------------------------------------
#define OFF_CX 768
#define OFF_CW 19200
#define CONV_SMEM 74496

extern __shared__ __align__(16) char smem_dyn[];

__global__ __launch_bounds__(256, 2)
void k_conv(const float* __restrict__ x, const float* __restrict__ bias) {
    char* smem = smem_dyn;
    float* sB = reinterpret_cast<float*>(smem);
    uint*  sX = reinterpret_cast<uint*>(smem + OFF_CX);
    uint*  sW = reinterpret_cast<uint*>(smem + OFF_CW);

    const int tid = threadIdx.x;
    const int p0  = blockIdx.x * 64;

    if (tid < 192) sB[tid] = __ldg(&bias[tid]);

    {
        const int pl = tid & 63;
        const int gr = tid >> 6;              // 0..3
        const int p  = p0 + pl;
        const int b  = p / 7500;
        const int q  = p - b * 7500;
        const float* xb = x + b * 480000 + q;
        #pragma unroll
        for (int j = 0; j < 16; ++j) {
            const int ci = gr * 16 + j;
            sX[pl * 72 + cperm(ci)] = f2tf(__ldg(xb + ci * 7500));
        }
    }
    for (int i = tid; i < 12288; i += 256) {
        const int o = i >> 6, ci = i & 63;
        sW[o * 72 + cperm(ci)] = g_Wt[i];
    }
    __syncthreads();

    const int wid  = tid >> 5;
    const int lane = tid & 31;
    const int mw = wid & 1;            // pixel rows mw*32
    const int nw = wid >> 1;           // o cols nw*48
    const int g  = lane >> 2;
    const int tt = lane & 3;

    float acc[2][6][4];
    #pragma unroll
    for (int nf = 0; nf < 6; ++nf) {
        const float b0 = sB[nw * 48 + nf * 8 + 2 * tt];
        const float b1 = sB[nw * 48 + nf * 8 + 2 * tt + 1];
        #pragma unroll
        for (int i = 0; i < 2; ++i) {
            acc[i][nf][0] = b0; acc[i][nf][1] = b1;
            acc[i][nf][2] = b0; acc[i][nf][3] = b1;
        }
    }

    const uint2* X2 = reinterpret_cast<const uint2*>(sX);   // row stride 36
    const uint2* W2 = reinterpret_cast<const uint2*>(sW);

    #pragma unroll 2
    for (int ks = 0; ks < 8; ++ks) {
        const int kj = ks * 4 + tt;
        uint a[2][4], bf[6][2];
        #pragma unroll
        for (int i = 0; i < 2; ++i) {
            const int row = mw * 32 + i * 16 + g;
            const uint2 lo = X2[row * 36 + kj];
            const uint2 hi = X2[(row + 8) * 36 + kj];
            a[i][0] = lo.x; a[i][2] = lo.y;
            a[i][1] = hi.x; a[i][3] = hi.y;
        }
        #pragma unroll
        for (int nf = 0; nf < 6; ++nf) {
            const uint2 w2 = W2[(nw * 48 + nf * 8 + g) * 36 + kj];
            bf[nf][0] = w2.x; bf[nf][1] = w2.y;
        }
        #pragma unroll
        for (int i = 0; i < 2; ++i)
            #pragma unroll
            for (int nf = 0; nf < 6; ++nf)
                mma_tf32(acc[i][nf], a[i], bf[nf]);
    }

    // epilogue: tf32 scatter into graph layout.
    // addr = b*1689600 + c*26400 + t*88 + cperm(k*26 + v)
    #pragma unroll
    for (int i = 0; i < 2; ++i) {
        const int p1 = p0 + mw * 32 + i * 16 + g;
        const int p2 = p1 + 8;
        const int b1i = p1 / 7500, q1 = p1 - b1i * 7500;
        const int t1  = q1 / 25,   v1 = q1 - t1 * 25;
        const int b2i = p2 / 7500, q2 = p2 - b2i * 7500;
        const int t2  = q2 / 25,   v2 = q2 - t2 * 25;
        uint* d1 = g_xc + b1i * 1689600 + t1 * 88;
        uint* d2 = g_xc + b2i * 1689600 + t2 * 88;
        #pragma unroll
        for (int nf = 0; nf < 6; ++nf) {
            const int o = nw * 48 + nf * 8 + 2 * tt;
            const int k = o >> 6, c = o & 63;
            const int col1 = cperm(k * 26 + v1);
            const int col2 = cperm(k * 26 + v2);
            d1[c * 26400 + col1]       = f2tf(acc[i][nf][0]);
            d1[(c + 1) * 26400 + col1] = f2tf(acc[i][nf][1]);
            d2[c * 26400 + col2]       = f2tf(acc[i][nf][2]);
            d2[(c + 1) * 26400 + col2] = f2tf(acc[i][nf][3]);
        }
    }
}

// ---------------------------------------------------------------------------
// k_graph: 128 rows x 32 w (25 live), K=80. 256 thr = 4 M-warps x 2 N-warps.
// Loader: pure uint4 copies (operands pre-formatted). BN stats from acc regs.
// smem: sX [128][88] uints (45056 B) | sA [32][88] (11264 B) = 56320 B.
// ---------------------------------------------------------------------------
#define OFF_GA 45056
#define GRAPH_SMEM 56320

__global__ __launch_bounds__(256)
void k_graph(float* __restrict__ out) {
    char* smem = smem_dyn;
    uint* sX = reinterpret_cast<uint*>(smem);
    uint* sA = reinterpret_cast<uint*>(smem + OFF_GA);

    const int tid = threadIdx.x;
    const int r0  = blockIdx.x * 128;

    // pure copies: X tile (2816 uint4) + A tile (704 uint4)
    {
        const uint4* xs = reinterpret_cast<const uint4*>(g_xc) + (size_t)r0 * 22;
        uint4* xd = reinterpret_cast<uint4*>(sX);
        for (int i = tid; i < 2816; i += 256) xd[i] = xs[i];
        const uint4* as = reinterpret_cast<const uint4*>(g_At);
        uint4* ad = reinterpret_cast<uint4*>(sA);
        for (int i = tid; i < 704; i += 256) ad[i] = as[i];
    }
    __syncthreads();

    const int wid  = tid >> 5;
    const int lane = tid & 31;
    const int mw = wid & 3;            // rows mw*32
    const int nw = wid >> 2;           // cols nw*16
    const int g  = lane >> 2;
    const int tt = lane & 3;

    float acc[2][2][4];
    #pragma unroll
    for (int i = 0; i < 2; ++i)
        #pragma unroll
        for (int j = 0; j < 2; ++j)
            #pragma unroll
            for (int z = 0; z < 4; ++z) acc[i][j][z] = 0.f;

    const uint2* X2 = reinterpret_cast<const uint2*>(sX);   // row stride 44
    const uint2* A2 = reinterpret_cast<const uint2*>(sA);

    #pragma unroll
    for (int ks = 0; ks < 10; ++ks) {
        const int kj = ks * 4 + tt;
        uint a[2][4], bb[2][2];
        #pragma unroll
        for (int i = 0; i < 2; ++i) {
            const int row = mw * 32 + i * 16 + g;
            const uint2 lo = X2[row * 44 + kj];
            const uint2 hi = X2[(row + 8) * 44 + kj];
            a[i][0] = lo.x; a[i][2] = lo.y;
            a[i][1] = hi.x; a[i][3] = hi.y;
        }
        #pragma unroll
        for (int j = 0; j < 2; ++j) {
            const uint2 w2 = A2[(nw * 16 + j * 8 + g) * 44 + kj];
            bb[j][0] = w2.x; bb[j][1] = w2.y;
        }
        #pragma unroll
        for (int i = 0; i < 2; ++i)
            #pragma unroll
            for (int j = 0; j < 2; ++j)
                mma_tf32(acc[i][j], a[i], bb[j]);
    }
    __syncthreads();                    // sX dead; reuse as sOut + red

    // stage sOut [128][25] packed + BN partials straight from registers
    float* sOut = reinterpret_cast<float*>(smem);
    float* red  = sOut + 3328;
    const int cidx = r0 / 300;
    const int rm   = r0 - cidx * 300;
    const int ib   = 300 - rm;          // local row boundary; >=128 -> one seg
    float s0 = 0.f, q0 = 0.f, s1 = 0.f, q1 = 0.f;
    #pragma unroll
    for (int i = 0; i < 2; ++i)
        #pragma unroll
        for (int j = 0; j < 2; ++j) {
            const int row = mw * 32 + i * 16 + g;
            const int col = nw * 16 + j * 8 + 2 * tt;
            if (col < 25) {
                const float v0 = acc[i][j][0], v2 = acc[i][j][2];
                sOut[row * 25 + col]       = v0;
                sOut[(row + 8) * 25 + col] = v2;
                if (row < ib)     { s0 += v0; q0 += v0 * v0; }
                else              { s1 += v0; q1 += v0 * v0; }
                if (row + 8 < ib) { s0 += v2; q0 += v2 * v2; }
                else              { s1 += v2; q1 += v2 * v2; }
                if (col + 1 < 25) {
                    const float v1 = acc[i][j][1], v3 = acc[i][j][3];
                    sOut[row * 25 + col + 1]       = v1;
                    sOut[(row + 8) * 25 + col + 1] = v3;
                    if (row < ib)     { s0 += v1; q0 += v1 * v1; }
                    else              { s1 += v1; q1 += v1 * v1; }
                    if (row + 8 < ib) { s0 += v3; q0 += v3 * v3; }
                    else              { s1 += v3; q1 += v3 * v3; }
                }
            }
        }
    red[tid] = s0; red[256 + tid] = q0; red[512 + tid] = s1; red[768 + tid] = q1;
    __syncthreads();

    // coalesced out store (pure float4 copy)
    {
        const float4* s4 = reinterpret_cast<const float4*>(sOut);
        float4* d4 = reinterpret_cast<float4*>(out + r0 * 25);
        for (int i = tid; i < 800; i += 256) d4[i] = s4[i];
    }
    // tree-reduce BN partials
    #pragma unroll
    for (int off = 128; off > 0; off >>= 1) {
        if (tid < off) {
            red[tid]       += red[tid + off];
            red[256 + tid] += red[256 + tid + off];
            red[512 + tid] += red[512 + tid + off];
            red[768 + tid] += red[768 + tid + off];
        }
        __syncthreads();
    }
    if (tid == 0) {
        const int slot = (rm + 127) >> 7;       // 0..3, collision-free
        g_bsum[cidx * 4 + slot] = red[0];
        g_bsq [cidx * 4 + slot] = red[256];
        if (ib < 128) {
            g_bsum[(cidx + 1) * 4] = red[512];
            g_bsq [(cidx + 1) * 4] = red[768];
        }
    }
}

// ---------------------------------------------------------------------------
// k_stats2: 64 blocks; 256 entries per channel (64 b x 4 slots), double.
// ---------------------------------------------------------------------------
__global__ __launch_bounds__(256) void k_stats2(const float* __restrict__ gamma,
                                                const float* __restrict__ beta) {
    const int c = blockIdx.x;
    __shared__ double ds[256], dq[256];
    const int b = threadIdx.x >> 2, s = threadIdx.x & 3;
    ds[threadIdx.x] = (double)g_bsum[(b * 64 + c) * 4 + s];
    dq[threadIdx.x] = (double)g_bsq [(b * 64 + c) * 4 + s];
    __syncthreads();
    #pragma unroll
    for (int off = 128; off > 0; off >>= 1) {
        if (threadIdx.x < off) {
            ds[threadIdx.x] += ds[threadIdx.x + off];
            dq[threadIdx.x] += dq[threadIdx.x + off];
        }
        __syncthreads();
    }
    if (threadIdx.x == 0) {
        const double mean = ds[0] / 480000.0;
        const double var  = dq[0] / 480000.0 - mean * mean;
        const double rstd = 1.0 / sqrt(var + 1e-5);
        const float sc = (float)((double)gamma[c] * rstd);
        g_scale[c] = sc;
        g_shift[c] = beta[c] - (float)mean * sc;
    }
}

// ---------------------------------------------------------------------------
__global__ __launch_bounds__(256) void k_bn(float* __restrict__ out) {
    const int i = blockIdx.x * 256 + threadIdx.x;
    if (i >= 7680000) return;
    const int c = (i / 1875) & 63;
    const float sc = g_scale[c];
    const float sh = g_shift[c];
    float4 v = reinterpret_cast<float4*>(out)[i];
    v.x = fmaf(v.x, sc, sh);
    v.y = fmaf(v.y, sc, sh);
    v.z = fmaf(v.z, sc, sh);
    v.w = fmaf(v.w, sc, sh);
    reinterpret_cast<float4*>(out)[i] = v;
}

// ---------------------------------------------------------------------------
extern "C" void kernel_launch(void* const* d_in, const int* in_sizes, int n_in,
                              void* d_out, int out_size) {
    const float* x     = (const float*)d_in[0];
    const float* W     = (const float*)d_in[1];
    const float* bias  = (const float*)d_in[2];
    const float* A     = (const float*)d_in[3];
    const float* gamma = (const float*)d_in[4];
    const float* beta  = (const float*)d_in[5];
    float* out = (float*)d_out;

    cudaFuncSetAttribute(k_conv,  cudaFuncAttributeMaxDynamicSharedMemorySize, CONV_SMEM);
    cudaFuncSetAttribute(k_graph, cudaFuncAttributeMaxDynamicSharedMemorySize, GRAPH_SMEM);

    // k_prep idempotent; 2 launches keep ncu capture slot on k_graph
    k_prep  <<<64, 256>>>(W, A);
    k_prep  <<<64, 256>>>(W, A);
    k_conv  <<<7500, 256, CONV_SMEM>>>(x, bias);
    k_graph <<<9600, 256, GRAPH_SMEM>>>(out);
    k_stats2<<<64, 256>>>(gamma, beta);
    k_bn    <<<30000, 256>>>(out);
}

// round 16
// speedup vs baseline: 1.0723x; 1.0723x over previous
#include <cuda_runtime.h>
#include <cuda_bf16.h>
#include <cstdint>

typedef unsigned int uint;

// ---------------------------------------------------------------------------
// B=64, Cin=64, T=300, V=25, K=3, Cout=64
//   x: [64][64][300][25]; W: [192][64] (o=k*64+c); A: [3][25][25]
//   out: [64][64][300][25]
// xc scratch: tf32 bits in GRAPH OPERAND LAYOUT [r][88]:
//   r = (b*64+c)*300 + t ; column = cperm(k*26+v); pads zero (static init,
//   never written). Graph loader = pure uint4 copy.
// Conv epilogue stages through SMEM so xc writes coalesce along v.
// Both GEMMs: mma.sync m16n8k8 TF32 (cvt.rna), pair-permuted LDS.64 operands.
// ---------------------------------------------------------------------------

__device__ uint  g_xc[108134400];         // 1228800 * 88 (432 MB)
__device__ float g_bsum[16384];           // [instance(b*64+c)][slot 0..3]
__device__ float g_bsq [16384];
__device__ float g_scale[64];
__device__ float g_shift[64];
__device__ uint  g_Wt[12288];             // W as tf32 bits, [o][ci]
__device__ uint  g_At[2816];              // A' tf32, [w 32][88] permuted, pads 0

__device__ __forceinline__ uint f2tf(float f) {
    uint u; asm("cvt.rna.tf32.f32 %0, %1;" : "=r"(u) : "f"(f)); return u;
}
__device__ __forceinline__ void mma_tf32(float* c, const uint* a, const uint* b) {
    asm volatile(
        "mma.sync.aligned.m16n8k8.row.col.f32.tf32.tf32.f32 "
        "{%0,%1,%2,%3}, {%4,%5,%6,%7}, {%8,%9}, {%0,%1,%2,%3};"
        : "+f"(c[0]), "+f"(c[1]), "+f"(c[2]), "+f"(c[3])
        : "r"(a[0]), "r"(a[1]), "r"(a[2]), "r"(a[3]), "r"(b[0]), "r"(b[1]));
}
// column permutation within each 8-group: [0,4,1,5,2,6,3,7]
__device__ __forceinline__ int cperm(int c) {
    return (c & ~7) | (((c & 3) << 1) | ((c & 4) >> 2));
}

// ---------------------------------------------------------------------------
// k_prep: W -> tf32; A -> permuted tf32 operand [32][88]; zero BN slots.
// Idempotent; launched 3x so ncu capture slot (launch index 3) = k_conv.
// ---------------------------------------------------------------------------
__global__ void k_prep(const float* __restrict__ W, const float* __restrict__ A) {
    const int i = blockIdx.x * 256 + threadIdx.x;
    if (i < 16384) { g_bsum[i] = 0.f; g_bsq[i] = 0.f; }
    if (i < 12288) g_Wt[i] = f2tf(W[i]);
    if (i < 2816) {
        const int w = i / 88, pc = i - w * 88;
        const int u = pc & 7;                        // inverse of cperm
        const int col = (pc & ~7) | ((u & 1) ? ((u >> 1) + 4) : (u >> 1));
        float val = 0.f;
        if (col < 80) {
            const int k = col / 26, v = col - 26 * k;
            if (w < 25 && k < 3 && v < 25) val = A[(k * 25 + v) * 25 + w];
        }
        g_At[i] = f2tf(val);
    }
}

// ---------------------------------------------------------------------------
// k_conv: 64 p x 192 o per CTA, K=64 tf32. 256 thr = 2 M-warps x 4 N-warps
// (warp tile 32x48). grid 7500, 2 CTAs/SM.
// smem: bias 768 | sX [64][72] tf32 | sW [192][72] tf32  (74496 B)
// Epilogue: accs -> sAcc [64][193] (reuses sX/sW region) -> coalesced STG.
// ---------------------------------------------------------------------------
#define OFF_CX 768
#define OFF_CW 19200
#define CONV_SMEM 74496

extern __shared__ __align__(16) char smem_dyn[];

__global__ __launch_bounds__(256, 2)
void k_conv(const float* __restrict__ x, const float* __restrict__ bias) {
    char* smem = smem_dyn;
    float* sB = reinterpret_cast<float*>(smem);
    uint*  sX = reinterpret_cast<uint*>(smem + OFF_CX);
    uint*  sW = reinterpret_cast<uint*>(smem + OFF_CW);

    const int tid = threadIdx.x;
    const int p0  = blockIdx.x * 64;

    if (tid < 192) sB[tid] = __ldg(&bias[tid]);

    {
        const int pl = tid & 63;
        const int gr = tid >> 6;              // 0..3
        const int p  = p0 + pl;
        const int b  = p / 7500;
        const int q  = p - b * 7500;
        const float* xb = x + b * 480000 + q;
        #pragma unroll
        for (int j = 0; j < 16; ++j) {
            const int ci = gr * 16 + j;
            sX[pl * 72 + cperm(ci)] = f2tf(__ldg(xb + ci * 7500));
        }
    }
    for (int i = tid; i < 12288; i += 256) {
        const int o = i >> 6, ci = i & 63;
        sW[o * 72 + cperm(ci)] = g_Wt[i];
    }
    __syncthreads();

    const int wid  = tid >> 5;
    const int lane = tid & 31;
    const int mw = wid & 1;            // pixel rows mw*32
    const int nw = wid >> 1;           // o cols nw*48
    const int g  = lane >> 2;
    const int tt = lane & 3;

    float acc[2][6][4];
    #pragma unroll
    for (int nf = 0; nf < 6; ++nf) {
        const float b0 = sB[nw * 48 + nf * 8 + 2 * tt];
        const float b1 = sB[nw * 48 + nf * 8 + 2 * tt + 1];
        #pragma unroll
        for (int i = 0; i < 2; ++i) {
            acc[i][nf][0] = b0; acc[i][nf][1] = b1;
            acc[i][nf][2] = b0; acc[i][nf][3] = b1;
        }
    }

    const uint2* X2 = reinterpret_cast<const uint2*>(sX);   // row stride 36
    const uint2* W2 = reinterpret_cast<const uint2*>(sW);

    #pragma unroll 2
    for (int ks = 0; ks < 8; ++ks) {
        const int kj = ks * 4 + tt;
        uint a[2][4], bf[6][2];
        #pragma unroll
        for (int i = 0; i < 2; ++i) {
            const int row = mw * 32 + i * 16 + g;
            const uint2 lo = X2[row * 36 + kj];
            const uint2 hi = X2[(row + 8) * 36 + kj];
            a[i][0] = lo.x; a[i][2] = lo.y;
            a[i][1] = hi.x; a[i][3] = hi.y;
        }
        #pragma unroll
        for (int nf = 0; nf < 6; ++nf) {
            const uint2 w2 = W2[(nw * 48 + nf * 8 + g) * 36 + kj];
            bf[nf][0] = w2.x; bf[nf][1] = w2.y;
        }
        #pragma unroll
        for (int i = 0; i < 2; ++i)
            #pragma unroll
            for (int nf = 0; nf < 6; ++nf)
                mma_tf32(acc[i][nf], a[i], bf[nf]);
    }
    __syncthreads();                    // operand tiles dead; reuse as sAcc

    // stage accs (already tf32) into sAcc[p][o], stride 193 (odd: LDS phase
    // conflict-free since lane = p there).
    uint* sAcc = reinterpret_cast<uint*>(smem + 768);
    #pragma unroll
    for (int i = 0; i < 2; ++i) {
        const int r1 = mw * 32 + i * 16 + g;
        #pragma unroll
        for (int nf = 0; nf < 6; ++nf) {
            const int o = nw * 48 + nf * 8 + 2 * tt;
            sAcc[r1 * 193 + o]           = f2tf(acc[i][nf][0]);
            sAcc[r1 * 193 + o + 1]       = f2tf(acc[i][nf][1]);
            sAcc[(r1 + 8) * 193 + o]     = f2tf(acc[i][nf][2]);
            sAcc[(r1 + 8) * 193 + o + 1] = f2tf(acc[i][nf][3]);
        }
    }
    __syncthreads();

    // coalesced store: group (tid>>5) owns 24 o's; lane owns pixels lane, lane+32.
    // addr = b*1689600 + c*26400 + t*88 + cperm(k*26+v)
    {
        const int grp = tid >> 5;
        const int oB  = grp * 24;
        int base[2], colk[2][3];
        #pragma unroll
        for (int h = 0; h < 2; ++h) {
            const int p = p0 + lane + 32 * h;
            const int b = p / 7500;
            const int q = p - b * 7500;
            const int t = q / 25;
            const int v = q - t * 25;
            base[h] = b * 1689600 + t * 88;
            #pragma unroll
            for (int k = 0; k < 3; ++k) colk[h][k] = cperm(k * 26 + v);
        }
        #pragma unroll 4
        for (int oo = 0; oo < 24; ++oo) {
            const int o = oB + oo;
            const int k = o >> 6, c = o & 63;
            const int coff = c * 26400;
            g_xc[base[0] + coff + colk[0][k]] = sAcc[lane * 193 + o];
            g_xc[base[1] + coff + colk[1][k]] = sAcc[(lane + 32) * 193 + o];
        }
    }
}

// ---------------------------------------------------------------------------
// k_graph (R15-exact, 172 us): 128 rows x 32 w, K=80. Pure-copy loader,
// BN stats from registers. smem: sX [128][88] | sA [32][88] = 56320 B.
// ---------------------------------------------------------------------------
#define OFF_GA 45056
#define GRAPH_SMEM 56320

__global__ __launch_bounds__(256)
void k_graph(float* __restrict__ out) {
    char* smem = smem_dyn;
    uint* sX = reinterpret_cast<uint*>(smem);
    uint* sA = reinterpret_cast<uint*>(smem + OFF_GA);

    const int tid = threadIdx.x;
    const int r0  = blockIdx.x * 128;

    {
        const uint4* xs = reinterpret_cast<const uint4*>(g_xc) + (size_t)r0 * 22;
        uint4* xd = reinterpret_cast<uint4*>(sX);
        for (int i = tid; i < 2816; i += 256) xd[i] = xs[i];
        const uint4* as = reinterpret_cast<const uint4*>(g_At);
        uint4* ad = reinterpret_cast<uint4*>(sA);
        for (int i = tid; i < 704; i += 256) ad[i] = as[i];
    }
    __syncthreads();

    const int wid  = tid >> 5;
    const int lane = tid & 31;
    const int mw = wid & 3;            // rows mw*32
    const int nw = wid >> 2;           // cols nw*16
    const int g  = lane >> 2;
    const int tt = lane & 3;

    float acc[2][2][4];
    #pragma unroll
    for (int i = 0; i < 2; ++i)
        #pragma unroll
        for (int j = 0; j < 2; ++j)
            #pragma unroll
            for (int z = 0; z < 4; ++z) acc[i][j][z] = 0.f;

    const uint2* X2 = reinterpret_cast<const uint2*>(sX);   // row stride 44
    const uint2* A2 = reinterpret_cast<const uint2*>(sA);

    #pragma unroll
    for (int ks = 0; ks < 10; ++ks) {
        const int kj = ks * 4 + tt;
        uint a[2][4], bb[2][2];
        #pragma unroll
        for (int i = 0; i < 2; ++i) {
            const int row = mw * 32 + i * 16 + g;
            const uint2 lo = X2[row * 44 + kj];
            const uint2 hi = X2[(row + 8) * 44 + kj];
            a[i][0] = lo.x; a[i][2] = lo.y;
            a[i][1] = hi.x; a[i][3] = hi.y;
        }
        #pragma unroll
        for (int j = 0; j < 2; ++j) {
            const uint2 w2 = A2[(nw * 16 + j * 8 + g) * 44 + kj];
            bb[j][0] = w2.x; bb[j][1] = w2.y;
        }
        #pragma unroll
        for (int i = 0; i < 2; ++i)
            #pragma unroll
            for (int j = 0; j < 2; ++j)
                mma_tf32(acc[i][j], a[i], bb[j]);
    }
    __syncthreads();                    // sX dead; reuse as sOut + red

    float* sOut = reinterpret_cast<float*>(smem);
    float* red  = sOut + 3328;
    const int cidx = r0 / 300;
    const int rm   = r0 - cidx * 300;
    const int ib   = 300 - rm;          // local row boundary; >=128 -> one seg
    float s0 = 0.f, q0 = 0.f, s1 = 0.f, q1 = 0.f;
    #pragma unroll
    for (int i = 0; i < 2; ++i)
        #pragma unroll
        for (int j = 0; j < 2; ++j) {
            const int row = mw * 32 + i * 16 + g;
            const int col = nw * 16 + j * 8 + 2 * tt;
            if (col < 25) {
                const float v0 = acc[i][j][0], v2 = acc[i][j][2];
                sOut[row * 25 + col]       = v0;
                sOut[(row + 8) * 25 + col] = v2;
                if (row < ib)     { s0 += v0; q0 += v0 * v0; }
                else              { s1 += v0; q1 += v0 * v0; }
                if (row + 8 < ib) { s0 += v2; q0 += v2 * v2; }
                else              { s1 += v2; q1 += v2 * v2; }
                if (col + 1 < 25) {
                    const float v1 = acc[i][j][1], v3 = acc[i][j][3];
                    sOut[row * 25 + col + 1]       = v1;
                    sOut[(row + 8) * 25 + col + 1] = v3;
                    if (row < ib)     { s0 += v1; q0 += v1 * v1; }
                    else              { s1 += v1; q1 += v1 * v1; }
                    if (row + 8 < ib) { s0 += v3; q0 += v3 * v3; }
                    else              { s1 += v3; q1 += v3 * v3; }
                }
            }
        }
    red[tid] = s0; red[256 + tid] = q0; red[512 + tid] = s1; red[768 + tid] = q1;
    __syncthreads();

    {
        const float4* s4 = reinterpret_cast<const float4*>(sOut);
        float4* d4 = reinterpret_cast<float4*>(out + r0 * 25);
        for (int i = tid; i < 800; i += 256) d4[i] = s4[i];
    }
    #pragma unroll
    for (int off = 128; off > 0; off >>= 1) {
        if (tid < off) {
            red[tid]       += red[tid + off];
            red[256 + tid] += red[256 + tid + off];
            red[512 + tid] += red[512 + tid + off];
            red[768 + tid] += red[768 + tid + off];
        }
        __syncthreads();
    }
    if (tid == 0) {
        const int slot = (rm + 127) >> 7;       // 0..3, collision-free
        g_bsum[cidx * 4 + slot] = red[0];
        g_bsq [cidx * 4 + slot] = red[256];
        if (ib < 128) {
            g_bsum[(cidx + 1) * 4] = red[512];
            g_bsq [(cidx + 1) * 4] = red[768];
        }
    }
}

// ---------------------------------------------------------------------------
// k_stats2: 64 blocks; 256 entries per channel (64 b x 4 slots), double.
// ---------------------------------------------------------------------------
__global__ __launch_bounds__(256) void k_stats2(const float* __restrict__ gamma,
                                                const float* __restrict__ beta) {
    const int c = blockIdx.x;
    __shared__ double ds[256], dq[256];
    const int b = threadIdx.x >> 2, s = threadIdx.x & 3;
    ds[threadIdx.x] = (double)g_bsum[(b * 64 + c) * 4 + s];
    dq[threadIdx.x] = (double)g_bsq [(b * 64 + c) * 4 + s];
    __syncthreads();
    #pragma unroll
    for (int off = 128; off > 0; off >>= 1) {
        if (threadIdx.x < off) {
            ds[threadIdx.x] += ds[threadIdx.x + off];
            dq[threadIdx.x] += dq[threadIdx.x + off];
        }
        __syncthreads();
    }
    if (threadIdx.x == 0) {
        const double mean = ds[0] / 480000.0;
        const double var  = dq[0] / 480000.0 - mean * mean;
        const double rstd = 1.0 / sqrt(var + 1e-5);
        const float sc = (float)((double)gamma[c] * rstd);
        g_scale[c] = sc;
        g_shift[c] = beta[c] - (float)mean * sc;
    }
}

// ---------------------------------------------------------------------------
__global__ __launch_bounds__(256) void k_bn(float* __restrict__ out) {
    const int i = blockIdx.x * 256 + threadIdx.x;
    if (i >= 7680000) return;
    const int c = (i / 1875) & 63;
    const float sc = g_scale[c];
    const float sh = g_shift[c];
    float4 v = reinterpret_cast<float4*>(out)[i];
    v.x = fmaf(v.x, sc, sh);
    v.y = fmaf(v.y, sc, sh);
    v.z = fmaf(v.z, sc, sh);
    v.w = fmaf(v.w, sc, sh);
    reinterpret_cast<float4*>(out)[i] = v;
}

// ---------------------------------------------------------------------------
extern "C" void kernel_launch(void* const* d_in, const int* in_sizes, int n_in,
                              void* d_out, int out_size) {
    const float* x     = (const float*)d_in[0];
    const float* W     = (const float*)d_in[1];
    const float* bias  = (const float*)d_in[2];
    const float* A     = (const float*)d_in[3];
    const float* gamma = (const float*)d_in[4];
    const float* beta  = (const float*)d_in[5];
    float* out = (float*)d_out;

    cudaFuncSetAttribute(k_conv,  cudaFuncAttributeMaxDynamicSharedMemorySize, CONV_SMEM);
    cudaFuncSetAttribute(k_graph, cudaFuncAttributeMaxDynamicSharedMemorySize, GRAPH_SMEM);

    // k_prep idempotent; 3 launches put ncu capture slot (index 3) on k_conv
    k_prep  <<<64, 256>>>(W, A);
    k_prep  <<<64, 256>>>(W, A);
    k_prep  <<<64, 256>>>(W, A);
    k_conv  <<<7500, 256, CONV_SMEM>>>(x, bias);
    k_graph <<<9600, 256, GRAPH_SMEM>>>(out);
    k_stats2<<<64, 256>>>(gamma, beta);
    k_bn    <<<30000, 256>>>(out);
}